// round 1
// baseline (speedup 1.0000x reference)
#include <cuda_runtime.h>
#include <math.h>

// Problem constants
#define Bv 16
#define Nv 128
#define Dv 256
#define Hv 8
#define BM (Bv*Nv)                               // 2048 (b,m) pairs
#define EDGE_ELEMS ((size_t)Bv*Nv*Nv*Dv)         // 67108864
#define INV_SQRT_DK 0.17677669529663688f         // 1/sqrt(32)

// Scratch (device globals — no runtime allocation allowed)
__device__ float g_WqT[Dv*Dv];
__device__ float g_WkT[Dv*Dv];
__device__ float g_WvT[Dv*Dv];
__device__ float g_WeT[Dv*Dv];
__device__ float g_WnT[Dv*Dv];
__device__ float g_qW[(size_t)BM*Hv*Dv];         // per (b,m,h): qW[j] = sum_dk q[h*32+dk]*Wk[h*32+dk, j] * inv_sqrt_dk
__device__ float g_vproj[(size_t)BM*Dv];         // v projection

__device__ __forceinline__ float mishf(float x) {
    float sp = (x > 20.0f) ? x : log1pf(expf(x));
    return x * tanhf(sp);
}

// ---------------------------------------------------------------------------
// Transpose a 256x256 weight matrix into one of the device scratch buffers.
// grid (8,8), block (32,8)
// ---------------------------------------------------------------------------
__global__ void transpose_kernel(const float* __restrict__ src, int which) {
    float* dst = (which == 0) ? g_WqT :
                 (which == 1) ? g_WkT :
                 (which == 2) ? g_WvT :
                 (which == 3) ? g_WeT : g_WnT;
    __shared__ float t[32][33];
    int x0 = blockIdx.x * 32, y0 = blockIdx.y * 32;
    int tx = threadIdx.x, ty = threadIdx.y;
    #pragma unroll
    for (int i = 0; i < 32; i += 8)
        t[ty + i][tx] = src[(y0 + ty + i) * Dv + x0 + tx];
    __syncthreads();
    #pragma unroll
    for (int i = 0; i < 32; i += 8)
        dst[(x0 + ty + i) * Dv + y0 + tx] = t[tx][ty + i];
}

// ---------------------------------------------------------------------------
// Per-(b,m) prep: q projection -> qW (folded with Wk blocks, pre-scaled),
// v projection -> g_vproj. grid 2048, block 256.
// ---------------------------------------------------------------------------
__global__ void prep_kernel(const float* __restrict__ qn, const float* __restrict__ vn,
                            const float* __restrict__ Wk,
                            const float* __restrict__ bq, const float* __restrict__ bv) {
    int bm = blockIdx.x, tid = threadIdx.x;
    __shared__ float sRow[Dv];
    __shared__ float sQp[Dv];

    // q projection: q[d] = bq[d] + sum_j qn[j] * Wq[d,j]  (WqT[j,d] coalesced)
    sRow[tid] = qn[(size_t)bm * Dv + tid];
    __syncthreads();
    float acc = bq[tid];
    for (int j = 0; j < Dv; ++j) acc += sRow[j] * g_WqT[j * Dv + tid];
    sQp[tid] = acc;
    __syncthreads();

    // v projection
    sRow[tid] = vn[(size_t)bm * Dv + tid];
    __syncthreads();
    float accv = bv[tid];
    for (int j = 0; j < Dv; ++j) accv += sRow[j] * g_WvT[j * Dv + tid];
    g_vproj[(size_t)bm * Dv + tid] = accv;

    // qW[h][j] = (sum_dk q[h*32+dk] * Wk[h*32+dk, j]) * inv_sqrt_dk
    #pragma unroll
    for (int h = 0; h < Hv; ++h) {
        float a = 0.0f;
        #pragma unroll
        for (int dk = 0; dk < 32; ++dk)
            a += sQp[h * 32 + dk] * Wk[(h * 32 + dk) * Dv + tid];
        g_qW[((size_t)bm * Hv + h) * Dv + tid] = a * INV_SQRT_DK;
    }
}

// ---------------------------------------------------------------------------
// Main fused kernel: one CTA per (b,m). 256 threads.
//   stage 1: scores[h][n] = qW[h] . key_edge[b,m,n,:]   (chunks of 32 rows)
//   stage 2: softmax over n per head
//   stage 3: node path: mish((attn @ vproj) @ Wn^T + bn)
//   stage 4: per 32-row chunk: k = KE@Wk^T+bk ; k *= attn ; out = mish(k@We^T+be)
// Dynamic smem layout (floats):
//   sQW   [8*257]     (padded to kill bank conflicts)
//   sA    [32*260]    (KE chunk, later overwritten with scaled k)
//   sW    [32*260]    (weight j-tile)
//   sAttn [8*128]
//   sNode [256]
// ---------------------------------------------------------------------------
#define SMEM_FLOATS (8*257 + 32*260 + 32*260 + 8*128 + 256)

__global__ void __launch_bounds__(256, 2) main_kernel(
    const float* __restrict__ key_edge,
    const float* __restrict__ bk, const float* __restrict__ be,
    const float* __restrict__ bn,
    float* __restrict__ out)
{
    extern __shared__ float sm[];
    float* sQW   = sm;                   // 8*257
    float* sA    = sQW + 8 * 257;        // 32*260
    float* sW    = sA + 32 * 260;        // 32*260
    float* sAttn = sW + 32 * 260;        // 8*128
    float* sNode = sAttn + 8 * 128;      // 256

    const int tid  = threadIdx.x;
    const int lane = tid & 31;
    const int warp = tid >> 5;
    const int bm   = blockIdx.x;
    const int b    = bm >> 7;

    // load (pre-scaled) qW into smem
    for (int i = tid; i < Hv * Dv; i += 256)
        sQW[(i >> 8) * 257 + (i & 255)] = g_qW[(size_t)bm * (Hv * Dv) + i];

    const float* keb = key_edge + (size_t)bm * (Nv * Dv);
    const int r4 = tid >> 6;          // row-within-4 group for float4 loads
    const int c4 = (tid & 63) * 4;    // column (floats) for float4 loads

    // ---------------- stage 1: scores ----------------
    for (int c = 0; c < 4; ++c) {
        __syncthreads();
        #pragma unroll
        for (int rr = 0; rr < 32; rr += 4) {
            float4 t4 = *(const float4*)&keb[(size_t)(c * 32 + rr + r4) * Dv + c4];
            *(float4*)&sA[(rr + r4) * 260 + c4] = t4;
        }
        __syncthreads();
        #pragma unroll
        for (int r = 0; r < 4; ++r) {
            int nl = warp * 4 + r;
            const float* arow = &sA[nl * 260];
            float p[8];
            #pragma unroll
            for (int h = 0; h < 8; ++h) p[h] = 0.0f;
            #pragma unroll
            for (int t = 0; t < 8; ++t) {
                int j = lane + 32 * t;
                float a = arow[j];
                #pragma unroll
                for (int h = 0; h < 8; ++h) p[h] += a * sQW[h * 257 + j];
            }
            #pragma unroll
            for (int h = 0; h < 8; ++h) {
                #pragma unroll
                for (int off = 16; off > 0; off >>= 1)
                    p[h] += __shfl_xor_sync(0xffffffffu, p[h], off);
            }
            if (lane == 0) {
                #pragma unroll
                for (int h = 0; h < 8; ++h)
                    sAttn[h * 128 + c * 32 + nl] = p[h];
            }
        }
    }
    __syncthreads();

    // ---------------- stage 2: softmax (warp per head) ----------------
    {
        int h = warp;
        float s[4];
        #pragma unroll
        for (int i = 0; i < 4; ++i) s[i] = sAttn[h * 128 + lane + 32 * i];
        float mx = fmaxf(fmaxf(s[0], s[1]), fmaxf(s[2], s[3]));
        #pragma unroll
        for (int off = 16; off > 0; off >>= 1)
            mx = fmaxf(mx, __shfl_xor_sync(0xffffffffu, mx, off));
        float e[4], sum = 0.0f;
        #pragma unroll
        for (int i = 0; i < 4; ++i) { e[i] = expf(s[i] - mx); sum += e[i]; }
        #pragma unroll
        for (int off = 16; off > 0; off >>= 1)
            sum += __shfl_xor_sync(0xffffffffu, sum, off);
        float inv = 1.0f / sum;
        #pragma unroll
        for (int i = 0; i < 4; ++i) sAttn[h * 128 + lane + 32 * i] = e[i] * inv;
    }
    __syncthreads();

    // ---------------- stage 3: node path ----------------
    {
        int h = tid >> 5;
        const float* vp = g_vproj + (size_t)b * Nv * Dv + tid;
        float acc = 0.0f;
        for (int n = 0; n < Nv; ++n)
            acc += sAttn[h * 128 + n] * vp[(size_t)n * Dv];
        sNode[tid] = acc;
        __syncthreads();
        float acc2 = bn[tid];
        for (int d = 0; d < Dv; ++d)
            acc2 += sNode[d] * g_WnT[d * Dv + tid];
        out[EDGE_ELEMS + (size_t)bm * Dv + tid] = mishf(acc2);
    }

    // ---------------- stage 4: edge path ----------------
    const int tr = tid >> 6;      // 0..3 : owns rows tr*8 .. tr*8+7 of chunk
    const int tc = tid & 63;      // 0..63: owns cols tc*4 .. tc*4+3
    const int hc = tc >> 3;       // head for this column group
    const float4 bk4 = *(const float4*)&bk[tc * 4];
    const float4 be4 = *(const float4*)&be[tc * 4];

    for (int c = 0; c < 4; ++c) {
        __syncthreads();
        #pragma unroll
        for (int rr = 0; rr < 32; rr += 4) {
            float4 t4 = *(const float4*)&keb[(size_t)(c * 32 + rr + r4) * Dv + c4];
            *(float4*)&sA[(rr + r4) * 260 + c4] = t4;
        }

        // k projection: acc = KE_chunk @ Wk^T + bk
        float acc[8][4];
        #pragma unroll
        for (int i = 0; i < 8; ++i) {
            acc[i][0] = bk4.x; acc[i][1] = bk4.y; acc[i][2] = bk4.z; acc[i][3] = bk4.w;
        }
        for (int jt = 0; jt < Dv; jt += 32) {
            __syncthreads();
            #pragma unroll
            for (int rr = 0; rr < 32; rr += 4)
                *(float4*)&sW[(rr + r4) * 260 + c4] =
                    *(const float4*)&g_WkT[(jt + rr + r4) * Dv + c4];
            __syncthreads();
            #pragma unroll
            for (int jj = 0; jj < 32; ++jj) {
                float4 w = *(float4*)&sW[jj * 260 + tc * 4];
                #pragma unroll
                for (int i = 0; i < 8; ++i) {
                    float a = sA[(tr * 8 + i) * 260 + jt + jj];
                    acc[i][0] += a * w.x; acc[i][1] += a * w.y;
                    acc[i][2] += a * w.z; acc[i][3] += a * w.w;
                }
            }
        }
        __syncthreads();

        // scale by attention, write scaled k back into sA
        #pragma unroll
        for (int i = 0; i < 8; ++i) {
            int n = c * 32 + tr * 8 + i;
            float at = sAttn[hc * 128 + n];
            float4 v4;
            v4.x = acc[i][0] * at; v4.y = acc[i][1] * at;
            v4.z = acc[i][2] * at; v4.w = acc[i][3] * at;
            *(float4*)&sA[(tr * 8 + i) * 260 + tc * 4] = v4;
        }

        // edge output: out = mish( scaled_k @ We^T + be )
        float acc2[8][4];
        #pragma unroll
        for (int i = 0; i < 8; ++i) {
            acc2[i][0] = be4.x; acc2[i][1] = be4.y; acc2[i][2] = be4.z; acc2[i][3] = be4.w;
        }
        for (int jt = 0; jt < Dv; jt += 32) {
            __syncthreads();
            #pragma unroll
            for (int rr = 0; rr < 32; rr += 4)
                *(float4*)&sW[(rr + r4) * 260 + c4] =
                    *(const float4*)&g_WeT[(jt + rr + r4) * Dv + c4];
            __syncthreads();
            #pragma unroll
            for (int jj = 0; jj < 32; ++jj) {
                float4 w = *(float4*)&sW[jj * 260 + tc * 4];
                #pragma unroll
                for (int i = 0; i < 8; ++i) {
                    float a = sA[(tr * 8 + i) * 260 + jt + jj];
                    acc2[i][0] += a * w.x; acc2[i][1] += a * w.y;
                    acc2[i][2] += a * w.z; acc2[i][3] += a * w.w;
                }
            }
        }
        #pragma unroll
        for (int i = 0; i < 8; ++i) {
            size_t o = ((size_t)bm * Nv + c * 32 + tr * 8 + i) * Dv + tc * 4;
            float4 o4;
            o4.x = mishf(acc2[i][0]); o4.y = mishf(acc2[i][1]);
            o4.z = mishf(acc2[i][2]); o4.w = mishf(acc2[i][3]);
            *(float4*)&out[o] = o4;
        }
    }
}

// ---------------------------------------------------------------------------
extern "C" void kernel_launch(void* const* d_in, const int* in_sizes, int n_in,
                              void* d_out, int out_size) {
    (void)in_sizes; (void)n_in; (void)out_size;
    const float* qn = (const float*)d_in[0];   // query_node (16,128,256)
    const float* vn = (const float*)d_in[1];   // value_node (16,128,256)
    const float* ke = (const float*)d_in[2];   // key_edge (16,128,128,256)
    // d_in[3] = adj_matrix (unused by reference outputs)
    const float* Wq = (const float*)d_in[4];
    const float* bq = (const float*)d_in[5];
    const float* Wk = (const float*)d_in[6];
    const float* bk = (const float*)d_in[7];
    const float* Wv = (const float*)d_in[8];
    const float* bv = (const float*)d_in[9];
    const float* We = (const float*)d_in[10];
    const float* be = (const float*)d_in[11];
    const float* Wn = (const float*)d_in[12];
    const float* bn = (const float*)d_in[13];
    // d_in[14] = attenuation_lambda (unused by reference outputs)
    float* out = (float*)d_out;

    dim3 tg(8, 8), tb(32, 8);
    transpose_kernel<<<tg, tb>>>(Wq, 0);
    transpose_kernel<<<tg, tb>>>(Wk, 1);
    transpose_kernel<<<tg, tb>>>(Wv, 2);
    transpose_kernel<<<tg, tb>>>(We, 3);
    transpose_kernel<<<tg, tb>>>(Wn, 4);

    prep_kernel<<<BM, 256>>>(qn, vn, Wk, bq, bv);

    size_t smem = SMEM_FLOATS * sizeof(float);
    cudaFuncSetAttribute(main_kernel, cudaFuncAttributeMaxDynamicSharedMemorySize, (int)smem);
    main_kernel<<<BM, 256, smem>>>(ke, bk, be, bn, out);
}

// round 2
// speedup vs baseline: 2.0365x; 2.0365x over previous
#include <cuda_runtime.h>
#include <cuda_fp16.h>
#include <math.h>

// Problem constants
#define Bv 16
#define Nv 128
#define Dv 256
#define Hv 8
#define BM (Bv*Nv)                               // 2048 (b,m) pairs
#define EDGE_ELEMS ((size_t)Bv*Nv*Nv*Dv)         // 67108864
#define INV_SQRT_DK 0.17677669529663688f         // 1/sqrt(32)

// Scratch (device globals — no runtime allocation allowed)
__device__ float g_WqT[Dv*Dv];
__device__ float g_WvT[Dv*Dv];
__device__ float g_WnT[Dv*Dv];
__device__ float g_qW[(size_t)BM*Hv*Dv];         // per (b,m,h): folded q@Wk, pre-scaled
__device__ float g_vproj[(size_t)BM*Dv];         // v projection
// Weight fragments for mma.sync m16n8k16: [kt][n8-tile][lane] = (hi0,hi1,lo0,lo1)
__device__ uint4 g_fragK[16][32][32];
__device__ uint4 g_fragE[16][32][32];

__device__ __forceinline__ float mishf(float x) {
    float sp = (x > 20.0f) ? x : log1pf(expf(x));
    return x * tanhf(sp);
}

__device__ __forceinline__ unsigned h2u(__half a, __half b) {
    return (unsigned)__half_as_ushort(a) | ((unsigned)__half_as_ushort(b) << 16);
}

__device__ __forceinline__ void mma16816(float* d, unsigned a0, unsigned a1,
                                         unsigned a2, unsigned a3,
                                         unsigned b0, unsigned b1) {
    asm volatile(
        "mma.sync.aligned.m16n8k16.row.col.f32.f16.f16.f32 "
        "{%0,%1,%2,%3},{%4,%5,%6,%7},{%8,%9},{%0,%1,%2,%3};"
        : "+f"(d[0]), "+f"(d[1]), "+f"(d[2]), "+f"(d[3])
        : "r"(a0), "r"(a1), "r"(a2), "r"(a3), "r"(b0), "r"(b1));
}

// ---------------------------------------------------------------------------
// Transpose a 256x256 weight matrix into a device scratch buffer.
// grid (8,8), block (32,8). which: 0=Wq, 1=Wv, 2=Wn
// ---------------------------------------------------------------------------
__global__ void transpose_kernel(const float* __restrict__ src, int which) {
    float* dst = (which == 0) ? g_WqT : (which == 1) ? g_WvT : g_WnT;
    __shared__ float t[32][33];
    int x0 = blockIdx.x * 32, y0 = blockIdx.y * 32;
    int tx = threadIdx.x, ty = threadIdx.y;
    #pragma unroll
    for (int i = 0; i < 32; i += 8)
        t[ty + i][tx] = src[(y0 + ty + i) * Dv + x0 + tx];
    __syncthreads();
    #pragma unroll
    for (int i = 0; i < 32; i += 8)
        dst[(x0 + ty + i) * Dv + y0 + tx] = t[tx][ty + i];
}

// ---------------------------------------------------------------------------
// Build hi/lo fp16 weight fragments in the exact mma.sync B register layout.
// grid (16,32,2), block 32. B[k][n] = W[n][k]; frag: n = tile*8 + lane/4,
// k0 = kt*16 + (lane%4)*2. uint4 = (hi(k0,k0+1), hi(k0+8,k0+9), lo..., lo...)
// ---------------------------------------------------------------------------
__global__ void fragprep_kernel(const float* __restrict__ Wk,
                                const float* __restrict__ We) {
    int lane = threadIdx.x;
    int kt = blockIdx.x, tile = blockIdx.y, mat = blockIdx.z;
    const float* W = mat ? We : Wk;
    int n  = tile * 8 + (lane >> 2);
    int k0 = kt * 16 + (lane & 3) * 2;

    float x0 = W[n * Dv + k0],     x1 = W[n * Dv + k0 + 1];
    float x8 = W[n * Dv + k0 + 8], x9 = W[n * Dv + k0 + 9];
    __half h0 = __float2half_rn(x0), h1 = __float2half_rn(x1);
    __half h8 = __float2half_rn(x8), h9 = __float2half_rn(x9);
    __half l0 = __float2half_rn(x0 - __half2float(h0));
    __half l1 = __float2half_rn(x1 - __half2float(h1));
    __half l8 = __float2half_rn(x8 - __half2float(h8));
    __half l9 = __float2half_rn(x9 - __half2float(h9));

    uint4 f;
    f.x = h2u(h0, h1); f.y = h2u(h8, h9);
    f.z = h2u(l0, l1); f.w = h2u(l8, l9);
    if (mat) g_fragE[kt][tile][lane] = f;
    else     g_fragK[kt][tile][lane] = f;
}

// ---------------------------------------------------------------------------
// Per-(b,m) prep: q projection folded with Wk blocks (pre-scaled) -> g_qW,
// v projection -> g_vproj. grid 2048, block 256.
// ---------------------------------------------------------------------------
__global__ void prep_kernel(const float* __restrict__ qn, const float* __restrict__ vn,
                            const float* __restrict__ Wk,
                            const float* __restrict__ bq, const float* __restrict__ bv) {
    int bm = blockIdx.x, tid = threadIdx.x;
    __shared__ float sRow[Dv];
    __shared__ float sQp[Dv];

    sRow[tid] = qn[(size_t)bm * Dv + tid];
    __syncthreads();
    float acc = bq[tid];
    for (int j = 0; j < Dv; ++j) acc += sRow[j] * g_WqT[j * Dv + tid];
    sQp[tid] = acc;
    __syncthreads();

    sRow[tid] = vn[(size_t)bm * Dv + tid];
    __syncthreads();
    float accv = bv[tid];
    for (int j = 0; j < Dv; ++j) accv += sRow[j] * g_WvT[j * Dv + tid];
    g_vproj[(size_t)bm * Dv + tid] = accv;

    #pragma unroll
    for (int h = 0; h < Hv; ++h) {
        float a = 0.0f;
        #pragma unroll
        for (int dk = 0; dk < 32; ++dk)
            a += sQp[h * 32 + dk] * Wk[(h * 32 + dk) * Dv + tid];
        g_qW[((size_t)bm * Hv + h) * Dv + tid] = a * INV_SQRT_DK;
    }
}

// ---------------------------------------------------------------------------
// Main fused kernel: one CTA per (b,m). 256 threads = 8 warps.
// smem (bytes):
//   sAhl : uint32[128][264]  KE packed (fp16 hi | lo<<16)          135168
//   union { sQW fp32[8][260] ; sK half[128][264] }                  67584
//   sAttn fp32[8][128]                                               4096
//   sNode fp32[256]                                                  1024
// total 207872
// ---------------------------------------------------------------------------
#define APITCH 264
#define SMEM_BYTES (128*APITCH*4 + 128*APITCH*2 + 8*128*4 + 256*4)

__global__ void __launch_bounds__(256, 1) main_kernel(
    const float* __restrict__ key_edge,
    const float* __restrict__ bk, const float* __restrict__ be,
    const float* __restrict__ bn,
    float* __restrict__ out)
{
    extern __shared__ char smraw[];
    unsigned*     sAhl  = (unsigned*)smraw;                          // 128*264 u32
    __half*       sK    = (__half*)(smraw + 128 * APITCH * 4);       // 128*264 half
    float*        sQW   = (float*)(smraw + 128 * APITCH * 4);        // union w/ sK
    float*        sAttn = (float*)(smraw + 128 * APITCH * 4 + 128 * APITCH * 2);
    float*        sNode = sAttn + 8 * 128;

    const int tid  = threadIdx.x;
    const int lane = tid & 31;
    const int warp = tid >> 5;
    const int bm   = blockIdx.x;
    const int b    = bm >> 7;

    // load pre-scaled qW into smem (fp32)
    for (int i = tid; i < Hv * Dv; i += 256)
        sQW[(i >> 8) * 260 + (i & 255)] = g_qW[(size_t)bm * (Hv * Dv) + i];

    // ------------- phase A: load KE once, pack fp16 hi/lo into smem -------------
    const float* keb = key_edge + (size_t)bm * (Nv * Dv);
    {
        const int r4 = tid >> 6;          // 0..3
        const int c4 = (tid & 63) * 4;    // 0..252
        #pragma unroll 4
        for (int row = r4; row < 128; row += 4) {
            float4 v = *(const float4*)&keb[(size_t)row * Dv + c4];
            uint4 p;
            __half h;
            h = __float2half_rn(v.x); p.x = h2u(h, __float2half_rn(v.x - __half2float(h)));
            h = __float2half_rn(v.y); p.y = h2u(h, __float2half_rn(v.y - __half2float(h)));
            h = __float2half_rn(v.z); p.z = h2u(h, __float2half_rn(v.z - __half2float(h)));
            h = __float2half_rn(v.w); p.w = h2u(h, __float2half_rn(v.w - __half2float(h)));
            *(uint4*)&sAhl[row * APITCH + c4] = p;
        }
    }
    __syncthreads();

    // ------------- phase B: scores from smem (hi+lo, near-fp32) -------------
    #pragma unroll 1
    for (int rr = 0; rr < 16; ++rr) {
        int n = warp * 16 + rr;
        const unsigned* arow = &sAhl[n * APITCH];
        float p[8];
        #pragma unroll
        for (int h = 0; h < 8; ++h) p[h] = 0.0f;
        #pragma unroll
        for (int t = 0; t < 8; ++t) {
            int j = lane + 32 * t;
            unsigned w = arow[j];
            __half2 h2 = *reinterpret_cast<__half2*>(&w);
            float a = __half2float(h2.x) + __half2float(h2.y);
            #pragma unroll
            for (int h = 0; h < 8; ++h) p[h] += a * sQW[h * 260 + j];
        }
        #pragma unroll
        for (int h = 0; h < 8; ++h) {
            #pragma unroll
            for (int off = 16; off > 0; off >>= 1)
                p[h] += __shfl_xor_sync(0xffffffffu, p[h], off);
        }
        if (lane == 0) {
            #pragma unroll
            for (int h = 0; h < 8; ++h) sAttn[h * 128 + n] = p[h];
        }
    }
    __syncthreads();

    // ------------- softmax (warp per head) -------------
    {
        int h = warp;
        float s[4];
        #pragma unroll
        for (int i = 0; i < 4; ++i) s[i] = sAttn[h * 128 + lane + 32 * i];
        float mx = fmaxf(fmaxf(s[0], s[1]), fmaxf(s[2], s[3]));
        #pragma unroll
        for (int off = 16; off > 0; off >>= 1)
            mx = fmaxf(mx, __shfl_xor_sync(0xffffffffu, mx, off));
        float e[4], sum = 0.0f;
        #pragma unroll
        for (int i = 0; i < 4; ++i) { e[i] = expf(s[i] - mx); sum += e[i]; }
        #pragma unroll
        for (int off = 16; off > 0; off >>= 1)
            sum += __shfl_xor_sync(0xffffffffu, sum, off);
        float inv = 1.0f / sum;
        #pragma unroll
        for (int i = 0; i < 4; ++i) sAttn[h * 128 + lane + 32 * i] = e[i] * inv;
    }
    __syncthreads();

    // ------------- node path -------------
    {
        int h = tid >> 5;
        const float* vp = g_vproj + (size_t)b * Nv * Dv + tid;
        float acc = 0.0f;
        for (int n = 0; n < Nv; ++n)
            acc += sAttn[h * 128 + n] * vp[(size_t)n * Dv];
        sNode[tid] = acc;
        __syncthreads();
        float acc2 = bn[tid];
        for (int d = 0; d < Dv; ++d)
            acc2 += sNode[d] * g_WnT[d * Dv + tid];
        out[EDGE_ELEMS + (size_t)bm * Dv + tid] = mishf(acc2);
    }
    __syncthreads();   // sAttn final; sQW no longer needed (sK may overwrite)

    // ------------- GEMM1: k = KE @ Wk^T (3-term hi/lo), scale, -> sK fp16 -------------
    const int wi = warp & 3;   // m-group: rows [wi*32, wi*32+32)
    const int wj = warp >> 2;  // n-group within pass: cols [wj*64, wj*64+64)
    const int rA = (lane >> 2);          // 0..7
    const int kq = (lane & 3) * 2;       // 0,2,4,6

    #pragma unroll 1
    for (int np = 0; np < 2; ++np) {
        float acc[2][8][4];
        #pragma unroll
        for (int mi = 0; mi < 2; ++mi)
            #pragma unroll
            for (int t = 0; t < 8; ++t)
                #pragma unroll
                for (int q = 0; q < 4; ++q) acc[mi][t][q] = 0.0f;

        #pragma unroll 1
        for (int kt = 0; kt < 16; ++kt) {
            unsigned ahi[2][4], alo[2][4];
            #pragma unroll
            for (int mi = 0; mi < 2; ++mi) {
                int r  = wi * 32 + mi * 16 + rA;
                int kc = kt * 16 + kq;
                uint2 w;
                w = *(const uint2*)&sAhl[r * APITCH + kc];
                ahi[mi][0] = __byte_perm(w.x, w.y, 0x5410);
                alo[mi][0] = __byte_perm(w.x, w.y, 0x7632);
                w = *(const uint2*)&sAhl[(r + 8) * APITCH + kc];
                ahi[mi][1] = __byte_perm(w.x, w.y, 0x5410);
                alo[mi][1] = __byte_perm(w.x, w.y, 0x7632);
                w = *(const uint2*)&sAhl[r * APITCH + kc + 8];
                ahi[mi][2] = __byte_perm(w.x, w.y, 0x5410);
                alo[mi][2] = __byte_perm(w.x, w.y, 0x7632);
                w = *(const uint2*)&sAhl[(r + 8) * APITCH + kc + 8];
                ahi[mi][3] = __byte_perm(w.x, w.y, 0x5410);
                alo[mi][3] = __byte_perm(w.x, w.y, 0x7632);
            }
            #pragma unroll
            for (int t = 0; t < 8; ++t) {
                uint4 bf = g_fragK[kt][np * 16 + wj * 8 + t][lane];
                #pragma unroll
                for (int mi = 0; mi < 2; ++mi) {
                    mma16816(acc[mi][t], ahi[mi][0], ahi[mi][1], ahi[mi][2], ahi[mi][3], bf.x, bf.y);
                    mma16816(acc[mi][t], alo[mi][0], alo[mi][1], alo[mi][2], alo[mi][3], bf.x, bf.y);
                    mma16816(acc[mi][t], ahi[mi][0], ahi[mi][1], ahi[mi][2], ahi[mi][3], bf.z, bf.w);
                }
            }
        }
        // epilogue: + bk, * attn, convert fp16 -> sK
        #pragma unroll
        for (int mi = 0; mi < 2; ++mi) {
            #pragma unroll
            for (int t = 0; t < 8; ++t) {
                int r0 = wi * 32 + mi * 16 + rA;
                int c  = np * 128 + wj * 64 + t * 8 + kq;
                float b0 = bk[c], b1 = bk[c + 1];
                const float* attc = &sAttn[(c >> 5) * 128];
                float a0 = attc[r0], a1 = attc[r0 + 8];
                __half2 h0 = __floats2half2_rn((acc[mi][t][0] + b0) * a0,
                                               (acc[mi][t][1] + b1) * a0);
                __half2 h1 = __floats2half2_rn((acc[mi][t][2] + b0) * a1,
                                               (acc[mi][t][3] + b1) * a1);
                *(__half2*)&sK[r0 * APITCH + c]       = h0;
                *(__half2*)&sK[(r0 + 8) * APITCH + c] = h1;
            }
        }
    }
    __syncthreads();   // sK complete

    // ------------- GEMM2: out = mish(sK @ We^T + be) (2-term) -------------
    #pragma unroll 1
    for (int np = 0; np < 2; ++np) {
        float acc[2][8][4];
        #pragma unroll
        for (int mi = 0; mi < 2; ++mi)
            #pragma unroll
            for (int t = 0; t < 8; ++t)
                #pragma unroll
                for (int q = 0; q < 4; ++q) acc[mi][t][q] = 0.0f;

        #pragma unroll 1
        for (int kt = 0; kt < 16; ++kt) {
            unsigned a[2][4];
            #pragma unroll
            for (int mi = 0; mi < 2; ++mi) {
                int r  = wi * 32 + mi * 16 + rA;
                int kc = kt * 16 + kq;
                a[mi][0] = *(const unsigned*)&sK[r * APITCH + kc];
                a[mi][1] = *(const unsigned*)&sK[(r + 8) * APITCH + kc];
                a[mi][2] = *(const unsigned*)&sK[r * APITCH + kc + 8];
                a[mi][3] = *(const unsigned*)&sK[(r + 8) * APITCH + kc + 8];
            }
            #pragma unroll
            for (int t = 0; t < 8; ++t) {
                uint4 bf = g_fragE[kt][np * 16 + wj * 8 + t][lane];
                #pragma unroll
                for (int mi = 0; mi < 2; ++mi) {
                    mma16816(acc[mi][t], a[mi][0], a[mi][1], a[mi][2], a[mi][3], bf.x, bf.y);
                    mma16816(acc[mi][t], a[mi][0], a[mi][1], a[mi][2], a[mi][3], bf.z, bf.w);
                }
            }
        }
        // epilogue: + be, mish, store (STG.64, 32B sectors fully covered)
        #pragma unroll
        for (int mi = 0; mi < 2; ++mi) {
            #pragma unroll
            for (int t = 0; t < 8; ++t) {
                int r0 = wi * 32 + mi * 16 + rA;
                int c  = np * 128 + wj * 64 + t * 8 + kq;
                float b0 = be[c], b1 = be[c + 1];
                float2 o0, o1;
                o0.x = mishf(acc[mi][t][0] + b0);
                o0.y = mishf(acc[mi][t][1] + b1);
                o1.x = mishf(acc[mi][t][2] + b0);
                o1.y = mishf(acc[mi][t][3] + b1);
                *(float2*)&out[((size_t)bm * Nv + r0) * Dv + c]       = o0;
                *(float2*)&out[((size_t)bm * Nv + r0 + 8) * Dv + c]   = o1;
            }
        }
    }
}

// ---------------------------------------------------------------------------
extern "C" void kernel_launch(void* const* d_in, const int* in_sizes, int n_in,
                              void* d_out, int out_size) {
    (void)in_sizes; (void)n_in; (void)out_size;
    const float* qn = (const float*)d_in[0];   // query_node (16,128,256)
    const float* vn = (const float*)d_in[1];   // value_node (16,128,256)
    const float* ke = (const float*)d_in[2];   // key_edge (16,128,128,256)
    // d_in[3] = adj_matrix (unused by reference outputs)
    const float* Wq = (const float*)d_in[4];
    const float* bq = (const float*)d_in[5];
    const float* Wk = (const float*)d_in[6];
    const float* bk = (const float*)d_in[7];
    // d_in[8] Wv, d_in[9] bv
    const float* Wv = (const float*)d_in[8];
    const float* bv = (const float*)d_in[9];
    const float* We = (const float*)d_in[10];
    const float* be = (const float*)d_in[11];
    const float* Wn = (const float*)d_in[12];
    const float* bn = (const float*)d_in[13];
    float* out = (float*)d_out;

    dim3 tg(8, 8), tb(32, 8);
    transpose_kernel<<<tg, tb>>>(Wq, 0);
    transpose_kernel<<<tg, tb>>>(Wv, 1);
    transpose_kernel<<<tg, tb>>>(Wn, 2);

    fragprep_kernel<<<dim3(16, 32, 2), 32>>>(Wk, We);
    prep_kernel<<<BM, 256>>>(qn, vn, Wk, bq, bv);

    size_t smem = SMEM_BYTES;
    cudaFuncSetAttribute(main_kernel, cudaFuncAttributeMaxDynamicSharedMemorySize, (int)smem);
    main_kernel<<<BM, 256, smem>>>(ke, bk, be, bn, out);
}

// round 4
// speedup vs baseline: 3.1582x; 1.5508x over previous
#include <cuda_runtime.h>
#include <cuda_fp16.h>
#include <math.h>
#include <stdint.h>

// ---------------- problem constants ----------------
#define Bv 16
#define Nv 128
#define Dv 256
#define Hv 8
#define BM (Bv*Nv)                               // 2048 (b,m) pairs
#define EDGE_ELEMS ((size_t)Bv*Nv*Nv*Dv)         // 67108864
#define INV_SQRT_DK 0.17677669529663688f

// ---------------- device scratch (no runtime alloc) ----------------
__device__ float g_WqT[Dv*Dv];
__device__ float g_WvT[Dv*Dv];
__device__ float g_WnT[Dv*Dv];
__device__ float g_qW[(size_t)BM*Hv*Dv];
__device__ float g_vproj[(size_t)BM*Dv];
// Single-fp16 B fragments for mma.m16n8k16: [(kt*32 + tile)*32 + lane] = (b0,b1)
__device__ uint2 g_fragK2[16*32*32];
__device__ uint2 g_fragE2[16*32*32];

__device__ __forceinline__ float mishf(float x) {
    float sp = (x > 20.0f) ? x : log1pf(expf(x));
    return x * tanhf(sp);
}
__device__ __forceinline__ unsigned h2u(__half a, __half b) {
    return (unsigned)__half_as_ushort(a) | ((unsigned)__half_as_ushort(b) << 16);
}
__device__ __forceinline__ uint32_t smem_u32(const void* p) {
    uint32_t a;
    asm("{ .reg .u64 t; cvta.to.shared.u64 t, %1; cvt.u32.u64 %0, t; }" : "=r"(a) : "l"(p));
    return a;
}
__device__ __forceinline__ void mma16816(float* d, unsigned a0, unsigned a1,
                                         unsigned a2, unsigned a3,
                                         unsigned b0, unsigned b1) {
    asm volatile(
        "mma.sync.aligned.m16n8k16.row.col.f32.f16.f16.f32 "
        "{%0,%1,%2,%3},{%4,%5,%6,%7},{%8,%9},{%0,%1,%2,%3};"
        : "+f"(d[0]), "+f"(d[1]), "+f"(d[2]), "+f"(d[3])
        : "r"(a0), "r"(a1), "r"(a2), "r"(a3), "r"(b0), "r"(b1));
}
__device__ __forceinline__ void ldsm_x4(unsigned* a, uint32_t addr) {
    asm volatile("ldmatrix.sync.aligned.m8n8.x4.shared.b16 {%0,%1,%2,%3}, [%4];"
        : "=r"(a[0]), "=r"(a[1]), "=r"(a[2]), "=r"(a[3]) : "r"(addr));
}

// ---------------- smem layout (bytes) ----------------
#define PITCH 264                                 // halfs per row of sA
#define SA_OFF    0                               // 128*264*2 = 67584 (fp16 A / A2)
#define SQW_OFF   67584                           // 8*260*4   = 8320
#define SATTN_OFF (SQW_OFF + 8*260*4)             // 4096
#define SNODE_OFF (SATTN_OFF + 4096)              // 1024
#define SBIAS_OFF (SNODE_OFF + 1024)              // 2048 (bk, be)
#define SMEM_TOTAL (SBIAS_OFF + 2048)             // 83072

// ---------------- prep kernels ----------------
__global__ void transpose_kernel(const float* __restrict__ src, int which) {
    float* dst = (which == 0) ? g_WqT : (which == 1) ? g_WvT : g_WnT;
    __shared__ float t[32][33];
    int x0 = blockIdx.x * 32, y0 = blockIdx.y * 32;
    int tx = threadIdx.x, ty = threadIdx.y;
    #pragma unroll
    for (int i = 0; i < 32; i += 8) t[ty + i][tx] = src[(y0 + ty + i) * Dv + x0 + tx];
    __syncthreads();
    #pragma unroll
    for (int i = 0; i < 32; i += 8) dst[(x0 + ty + i) * Dv + y0 + tx] = t[tx][ty + i];
}

// Build single-fp16 B fragments (b0,b1) per (kt, tile, lane).
// grid (16, 32, 2), block 32.
__global__ void fragprep_kernel(const float* __restrict__ Wk, const float* __restrict__ We) {
    int lane = threadIdx.x;
    int kt = blockIdx.x, tile = blockIdx.y, mat = blockIdx.z;
    const float* W = mat ? We : Wk;
    int n  = tile * 8 + (lane >> 2);
    int k0 = kt * 16 + (lane & 3) * 2;
    uint2 f;
    f.x = h2u(__float2half_rn(W[n * Dv + k0]),     __float2half_rn(W[n * Dv + k0 + 1]));
    f.y = h2u(__float2half_rn(W[n * Dv + k0 + 8]), __float2half_rn(W[n * Dv + k0 + 9]));
    int idx = (kt * 32 + tile) * 32 + lane;
    if (mat) g_fragE2[idx] = f;
    else     g_fragK2[idx] = f;
}

__global__ void prep_kernel(const float* __restrict__ qn, const float* __restrict__ vn,
                            const float* __restrict__ Wk,
                            const float* __restrict__ bq, const float* __restrict__ bv) {
    int bm = blockIdx.x, tid = threadIdx.x;
    __shared__ float sRow[Dv];
    __shared__ float sQp[Dv];
    sRow[tid] = qn[(size_t)bm * Dv + tid];
    __syncthreads();
    float acc = bq[tid];
    for (int j = 0; j < Dv; ++j) acc += sRow[j] * g_WqT[j * Dv + tid];
    sQp[tid] = acc;
    __syncthreads();
    sRow[tid] = vn[(size_t)bm * Dv + tid];
    __syncthreads();
    float accv = bv[tid];
    for (int j = 0; j < Dv; ++j) accv += sRow[j] * g_WvT[j * Dv + tid];
    g_vproj[(size_t)bm * Dv + tid] = accv;
    #pragma unroll
    for (int h = 0; h < Hv; ++h) {
        float a = 0.0f;
        #pragma unroll
        for (int dk = 0; dk < 32; ++dk)
            a += sQp[h * 32 + dk] * Wk[(h * 32 + dk) * Dv + tid];
        g_qW[((size_t)bm * Hv + h) * Dv + tid] = a * INV_SQRT_DK;
    }
}

// One np-pass of a 128x128x256 fp16 GEMM: acc[2][8][4] over 16 k-steps.
__device__ __forceinline__ void gemm_pass(float acc[2][8][4], uint32_t lm0, uint32_t lm1,
                                          const uint2* __restrict__ frag, int tBase, int lane) {
    #pragma unroll
    for (int mi = 0; mi < 2; ++mi)
        #pragma unroll
        for (int t = 0; t < 8; ++t)
            #pragma unroll
            for (int q = 0; q < 4; ++q) acc[mi][t][q] = 0.0f;

    #pragma unroll 1
    for (int kt = 0; kt < 16; ++kt) {
        const uint2* fp = frag + ((size_t)(kt * 32 + tBase)) * 32 + lane;
        uint2 bf[8];
        #pragma unroll
        for (int t = 0; t < 8; ++t) bf[t] = __ldg(fp + t * 32);
        unsigned a0[4], a1[4];
        ldsm_x4(a0, lm0 + kt * 32);
        ldsm_x4(a1, lm1 + kt * 32);
        #pragma unroll
        for (int t = 0; t < 8; ++t) {
            mma16816(acc[0][t], a0[0], a0[1], a0[2], a0[3], bf[t].x, bf[t].y);
            mma16816(acc[1][t], a1[0], a1[1], a1[2], a1[3], bf[t].x, bf[t].y);
        }
    }
}

// ---------------- main fused kernel: one CTA per (b,m), 256 threads ----------------
__global__ void __launch_bounds__(256, 2) main_kernel(
    const float* __restrict__ key_edge,
    const float* __restrict__ bk, const float* __restrict__ be,
    const float* __restrict__ bn,
    float* __restrict__ out)
{
    extern __shared__ char sm[];
    __half* sA   = (__half*)(sm + SA_OFF);
    float* sQW   = (float*)(sm + SQW_OFF);
    float* sAttn = (float*)(sm + SATTN_OFF);
    float* sNode = (float*)(sm + SNODE_OFF);
    float* sBk   = (float*)(sm + SBIAS_OFF);
    float* sBe   = sBk + 256;

    const int tid = threadIdx.x, lane = tid & 31, warp = tid >> 5;
    const int bm = blockIdx.x, b = bm >> 7;

    sBk[tid] = bk[tid];
    sBe[tid] = be[tid];
    for (int i = tid; i < Hv * Dv; i += 256)
        sQW[(i >> 8) * 260 + (i & 255)] = g_qW[(size_t)bm * (Hv * Dv) + i];

    // ---- phase 1: KE (fp32, global) -> sA (fp16) ----
    const float* keb = key_edge + (size_t)bm * (Nv * Dv);
    {
        const int r4 = tid >> 6, c4 = (tid & 63) * 4;
        #pragma unroll 4
        for (int rr = 0; rr < 128; rr += 4) {
            int row = rr + r4;
            float4 v = *(const float4*)&keb[(size_t)row * Dv + c4];
            uint2 p;
            __half2 h01 = __floats2half2_rn(v.x, v.y);
            __half2 h23 = __floats2half2_rn(v.z, v.w);
            p.x = *reinterpret_cast<unsigned*>(&h01);
            p.y = *reinterpret_cast<unsigned*>(&h23);
            *(uint2*)&sA[row * PITCH + c4] = p;
        }
    }
    __syncthreads();

    // ---- phase 2: scores (fp16 KE x fp32 qW), 16 rows per warp ----
    {
        float2 qreg[8][4];
        #pragma unroll
        for (int h = 0; h < 8; ++h)
            #pragma unroll
            for (int t = 0; t < 4; ++t)
                qreg[h][t] = *(float2*)&sQW[h * 260 + t * 64 + 2 * lane];

        #pragma unroll 1
        for (int rr = 0; rr < 16; ++rr) {
            int n = warp * 16 + rr;
            const __half* arow = &sA[n * PITCH];
            float p[8];
            #pragma unroll
            for (int h = 0; h < 8; ++h) p[h] = 0.0f;
            #pragma unroll
            for (int t = 0; t < 4; ++t) {
                unsigned w = *(const unsigned*)&arow[t * 64 + 2 * lane];
                float2 x = __half22float2(*reinterpret_cast<__half2*>(&w));
                #pragma unroll
                for (int h = 0; h < 8; ++h)
                    p[h] += x.x * qreg[h][t].x + x.y * qreg[h][t].y;
            }
            #pragma unroll
            for (int h = 0; h < 8; ++h) {
                #pragma unroll
                for (int off = 16; off > 0; off >>= 1)
                    p[h] += __shfl_xor_sync(0xffffffffu, p[h], off);
            }
            if (lane == 0) {
                #pragma unroll
                for (int h = 0; h < 8; ++h) sAttn[h * 128 + n] = p[h];
            }
        }
    }
    __syncthreads();

    // ---- softmax (warp per head) ----
    {
        int h = warp;
        float s[4];
        #pragma unroll
        for (int i = 0; i < 4; ++i) s[i] = sAttn[h * 128 + lane + 32 * i];
        float mx = fmaxf(fmaxf(s[0], s[1]), fmaxf(s[2], s[3]));
        #pragma unroll
        for (int off = 16; off > 0; off >>= 1)
            mx = fmaxf(mx, __shfl_xor_sync(0xffffffffu, mx, off));
        float e[4], sum = 0.0f;
        #pragma unroll
        for (int i = 0; i < 4; ++i) { e[i] = expf(s[i] - mx); sum += e[i]; }
        #pragma unroll
        for (int off = 16; off > 0; off >>= 1)
            sum += __shfl_xor_sync(0xffffffffu, sum, off);
        float inv = 1.0f / sum;
        #pragma unroll
        for (int i = 0; i < 4; ++i) sAttn[h * 128 + lane + 32 * i] = e[i] * inv;
    }
    __syncthreads();

    // ---- node path ----
    {
        int h = tid >> 5;
        const float* vp = g_vproj + (size_t)b * Nv * Dv + tid;
        float acc = 0.0f;
        for (int n = 0; n < Nv; ++n)
            acc += sAttn[h * 128 + n] * vp[(size_t)n * Dv];
        sNode[tid] = acc;
        __syncthreads();
        float acc2 = bn[tid];
        for (int d = 0; d < Dv; ++d)
            acc2 += sNode[d] * g_WnT[d * Dv + tid];
        out[EDGE_ELEMS + (size_t)bm * Dv + tid] = mishf(acc2);
    }
    __syncthreads();

    // ---- GEMM setup ----
    const int wi = warp & 3;                 // m-band: rows [wi*32, wi*32+32)
    const int wj = warp >> 2;                // n-group: cols [wj*64, wj*64+64) per np
    const int rA = lane >> 2;                // 0..7
    const int kq = (lane & 3) * 2;           // 0,2,4,6
    const int rowsel = (lane & 7) + ((lane >> 3) & 1) * 8;
    const int colsel = (lane >> 4) * 8;
    const uint32_t smbA = smem_u32(sA);
    const uint32_t lm0 = smbA + (uint32_t)(((wi * 32 + rowsel) * PITCH + colsel) * 2);
    const uint32_t lm1 = lm0 + 16 * PITCH * 2;

    float acc[2][8][4];
    unsigned pk0[2][8][2];

    // ---- GEMM1 np=0 ----
    gemm_pass(acc, lm0, lm1, g_fragK2, 0 * 16 + wj * 8, lane);
    #pragma unroll
    for (int mi = 0; mi < 2; ++mi) {
        #pragma unroll
        for (int t = 0; t < 8; ++t) {
            int r0 = wi * 32 + mi * 16 + rA;
            int c  = wj * 64 + t * 8 + kq;
            float b0 = sBk[c], b1 = sBk[c + 1];
            const float* attc = &sAttn[(c >> 5) * 128];
            float a0 = attc[r0], a8 = attc[r0 + 8];
            __half2 h0 = __floats2half2_rn((acc[mi][t][0] + b0) * a0, (acc[mi][t][1] + b1) * a0);
            __half2 h1 = __floats2half2_rn((acc[mi][t][2] + b0) * a8, (acc[mi][t][3] + b1) * a8);
            pk0[mi][t][0] = *reinterpret_cast<unsigned*>(&h0);
            pk0[mi][t][1] = *reinterpret_cast<unsigned*>(&h1);
        }
    }

    // ---- GEMM1 np=1 ----
    gemm_pass(acc, lm0, lm1, g_fragK2, 1 * 16 + wj * 8, lane);
    __syncthreads();   // all ldmatrix reads of sA (KE) complete

    // write A2 = scaled k (fp16) over sA
    #pragma unroll
    for (int mi = 0; mi < 2; ++mi) {
        #pragma unroll
        for (int t = 0; t < 8; ++t) {
            int r0 = wi * 32 + mi * 16 + rA;
            int c0 = wj * 64 + t * 8 + kq;            // np=0 column
            int c1 = 128 + c0;                        // np=1 column
            *(unsigned*)&sA[r0 * PITCH + c0]       = pk0[mi][t][0];
            *(unsigned*)&sA[(r0 + 8) * PITCH + c0] = pk0[mi][t][1];
            float b0 = sBk[c1], b1 = sBk[c1 + 1];
            const float* attc = &sAttn[(c1 >> 5) * 128];
            float a0 = attc[r0], a8 = attc[r0 + 8];
            __half2 h0 = __floats2half2_rn((acc[mi][t][0] + b0) * a0, (acc[mi][t][1] + b1) * a0);
            __half2 h1 = __floats2half2_rn((acc[mi][t][2] + b0) * a8, (acc[mi][t][3] + b1) * a8);
            *(unsigned*)&sA[r0 * PITCH + c1]       = *reinterpret_cast<unsigned*>(&h0);
            *(unsigned*)&sA[(r0 + 8) * PITCH + c1] = *reinterpret_cast<unsigned*>(&h1);
        }
    }
    __syncthreads();   // A2 visible to all warps

    // ---- GEMM2: out = mish(A2 @ We^T + be) ----
    #pragma unroll 1
    for (int np = 0; np < 2; ++np) {
        gemm_pass(acc, lm0, lm1, g_fragE2, np * 16 + wj * 8, lane);
        #pragma unroll
        for (int mi = 0; mi < 2; ++mi) {
            #pragma unroll
            for (int t = 0; t < 8; ++t) {
                int r0 = wi * 32 + mi * 16 + rA;
                int c  = np * 128 + wj * 64 + t * 8 + kq;
                float b0 = sBe[c], b1 = sBe[c + 1];
                float2 o0, o1;
                o0.x = mishf(acc[mi][t][0] + b0);
                o0.y = mishf(acc[mi][t][1] + b1);
                o1.x = mishf(acc[mi][t][2] + b0);
                o1.y = mishf(acc[mi][t][3] + b1);
                *(float2*)&out[((size_t)bm * Nv + r0) * Dv + c]     = o0;
                *(float2*)&out[((size_t)bm * Nv + r0 + 8) * Dv + c] = o1;
            }
        }
    }
}

// ---------------------------------------------------------------------------
extern "C" void kernel_launch(void* const* d_in, const int* in_sizes, int n_in,
                              void* d_out, int out_size) {
    (void)in_sizes; (void)n_in; (void)out_size;
    const float* qn = (const float*)d_in[0];
    const float* vn = (const float*)d_in[1];
    const float* ke = (const float*)d_in[2];
    const float* Wq = (const float*)d_in[4];
    const float* bq = (const float*)d_in[5];
    const float* Wk = (const float*)d_in[6];
    const float* bk = (const float*)d_in[7];
    const float* Wv = (const float*)d_in[8];
    const float* bv = (const float*)d_in[9];
    const float* We = (const float*)d_in[10];
    const float* be = (const float*)d_in[11];
    const float* Wn = (const float*)d_in[12];
    const float* bn = (const float*)d_in[13];
    float* out = (float*)d_out;

    dim3 tg(8, 8), tb(32, 8);
    transpose_kernel<<<tg, tb>>>(Wq, 0);
    transpose_kernel<<<tg, tb>>>(Wv, 1);
    transpose_kernel<<<tg, tb>>>(Wn, 2);
    fragprep_kernel<<<dim3(16, 32, 2), 32>>>(Wk, We);
    prep_kernel<<<BM, 256>>>(qn, vn, Wk, bq, bv);

    cudaFuncSetAttribute(main_kernel, cudaFuncAttributeMaxDynamicSharedMemorySize, SMEM_TOTAL);
    main_kernel<<<BM, 256, SMEM_TOTAL>>>(ke, bk, be, bn, out);
}

// round 5
// speedup vs baseline: 3.8990x; 1.2346x over previous
#include <cuda_runtime.h>
#include <cuda_fp16.h>
#include <math.h>
#include <stdint.h>

// ---------------- problem constants ----------------
#define Bv 16
#define Nv 128
#define Dv 256
#define Hv 8
#define BM (Bv*Nv)                               // 2048 (b,m) pairs
#define EDGE_ELEMS ((size_t)Bv*Nv*Nv*Dv)         // 67108864
#define INV_SQRT_DK 0.17677669529663688f

// ---------------- device scratch (no runtime alloc) ----------------
__device__ float g_WqT[Dv*Dv];
__device__ float g_WvT[Dv*Dv];
__device__ float g_WnT[Dv*Dv];
__device__ float g_qW[(size_t)BM*Hv*Dv];
__device__ float g_vproj[(size_t)BM*Dv];
// Single-fp16 B fragments for mma.m16n8k16: [(kt*32 + tile)*32 + lane] = (b0,b1)
__device__ uint2 g_fragK2[16*32*32];
__device__ uint2 g_fragE2[16*32*32];

// fast exact-identity mish: x*tanh(log1p(e^x)) == x*(u^2-1)/(u^2+1), u=1+e^x
__device__ __forceinline__ float mishf(float x) {
    if (x > 20.0f) return x;
    float t  = __expf(x);
    float u  = 1.0f + t;
    float u2 = u * u;
    return x * __fdividef(u2 - 1.0f, u2 + 1.0f);
}
__device__ __forceinline__ unsigned h2u(__half a, __half b) {
    return (unsigned)__half_as_ushort(a) | ((unsigned)__half_as_ushort(b) << 16);
}
__device__ __forceinline__ unsigned h2pack(__half2 h) {
    return *reinterpret_cast<unsigned*>(&h);
}
__device__ __forceinline__ uint32_t smem_u32(const void* p) {
    uint32_t a;
    asm("{ .reg .u64 t; cvta.to.shared.u64 t, %1; cvt.u32.u64 %0, t; }" : "=r"(a) : "l"(p));
    return a;
}
__device__ __forceinline__ void mma16816(float* d, unsigned a0, unsigned a1,
                                         unsigned a2, unsigned a3,
                                         unsigned b0, unsigned b1) {
    asm volatile(
        "mma.sync.aligned.m16n8k16.row.col.f32.f16.f16.f32 "
        "{%0,%1,%2,%3},{%4,%5,%6,%7},{%8,%9},{%0,%1,%2,%3};"
        : "+f"(d[0]), "+f"(d[1]), "+f"(d[2]), "+f"(d[3])
        : "r"(a0), "r"(a1), "r"(a2), "r"(a3), "r"(b0), "r"(b1));
}
__device__ __forceinline__ void ldsm_x4(unsigned* a, uint32_t addr) {
    asm volatile("ldmatrix.sync.aligned.m8n8.x4.shared.b16 {%0,%1,%2,%3}, [%4];"
        : "=r"(a[0]), "=r"(a[1]), "=r"(a[2]), "=r"(a[3]) : "r"(addr));
}

// ---------------- smem layout (bytes) ----------------
#define PITCH 264                                 // halfs per row of sA
#define SA_OFF    0                               // 128*264*2 = 67584 (fp16 A / A2)
#define SQW_OFF   67584                           // 8*260*4   = 8320
#define SATTN_OFF (SQW_OFF + 8*260*4)             // 4096
#define SNODE_OFF (SATTN_OFF + 4096)              // 1024
#define SBIAS_OFF (SNODE_OFF + 1024)              // 2048 (bk, be)
#define SMEM_TOTAL (SBIAS_OFF + 2048)             // 83072

// ---------------- K1: all weight prep in one launch ----------------
// blocks 0..191   : transposes of Wq/Wv/Wn (64 blocks each), block = 256 thr
// blocks 192..319 : fp16 B-fragment build for Wk and We
__global__ void wprep_kernel(const float* __restrict__ Wq, const float* __restrict__ Wv,
                             const float* __restrict__ Wn,
                             const float* __restrict__ Wk, const float* __restrict__ We) {
    int blk = blockIdx.x, tid = threadIdx.x;
    if (blk < 192) {
        int which = blk / 64, t2 = blk % 64;
        const float* src = (which == 0) ? Wq : (which == 1) ? Wv : Wn;
        float* dst = (which == 0) ? g_WqT : (which == 1) ? g_WvT : g_WnT;
        __shared__ float t[32][33];
        int x0 = (t2 & 7) * 32, y0 = (t2 >> 3) * 32;
        int tx = tid & 31, ty = tid >> 5;
        #pragma unroll
        for (int i = 0; i < 32; i += 8) t[ty + i][tx] = src[(y0 + ty + i) * Dv + x0 + tx];
        __syncthreads();
        #pragma unroll
        for (int i = 0; i < 32; i += 8) dst[(x0 + ty + i) * Dv + y0 + tx] = t[tx][ty + i];
    } else {
        int g = (blk - 192) * 256 + tid;          // 0..32767
        int mat = g >> 14;
        int r = g & 16383;
        int kt = r >> 10, tile = (r >> 5) & 31, lane = r & 31;
        const float* W = mat ? We : Wk;
        int n  = tile * 8 + (lane >> 2);
        int k0 = kt * 16 + (lane & 3) * 2;
        uint2 f;
        f.x = h2u(__float2half_rn(W[n * Dv + k0]),     __float2half_rn(W[n * Dv + k0 + 1]));
        f.y = h2u(__float2half_rn(W[n * Dv + k0 + 8]), __float2half_rn(W[n * Dv + k0 + 9]));
        int idx = (kt * 32 + tile) * 32 + lane;
        if (mat) g_fragE2[idx] = f;
        else     g_fragK2[idx] = f;
    }
}

// ---------------- K2: per-(b,m) q/v projections ----------------
__global__ void prep_kernel(const float* __restrict__ qn, const float* __restrict__ vn,
                            const float* __restrict__ Wk,
                            const float* __restrict__ bq, const float* __restrict__ bv) {
    int bm = blockIdx.x, tid = threadIdx.x;
    __shared__ float sRow[Dv];
    __shared__ float sQp[Dv];
    sRow[tid] = qn[(size_t)bm * Dv + tid];
    __syncthreads();
    float acc = bq[tid];
    for (int j = 0; j < Dv; ++j) acc += sRow[j] * g_WqT[j * Dv + tid];
    sQp[tid] = acc;
    __syncthreads();
    sRow[tid] = vn[(size_t)bm * Dv + tid];
    __syncthreads();
    float accv = bv[tid];
    for (int j = 0; j < Dv; ++j) accv += sRow[j] * g_WvT[j * Dv + tid];
    g_vproj[(size_t)bm * Dv + tid] = accv;
    #pragma unroll
    for (int h = 0; h < Hv; ++h) {
        float a = 0.0f;
        #pragma unroll
        for (int dk = 0; dk < 32; ++dk)
            a += sQp[h * 32 + dk] * Wk[(h * 32 + dk) * Dv + tid];
        g_qW[((size_t)bm * Hv + h) * Dv + tid] = a * INV_SQRT_DK;
    }
}

// One np-pass of a 128x128x256 fp16 GEMM. PF: register double-buffer B prefetch.
template <bool PF>
__device__ __forceinline__ void gemm_pass(float acc[2][8][4], uint32_t lm0, uint32_t lm1,
                                          const uint2* __restrict__ frag, int tBase, int lane) {
    #pragma unroll
    for (int mi = 0; mi < 2; ++mi)
        #pragma unroll
        for (int t = 0; t < 8; ++t)
            #pragma unroll
            for (int q = 0; q < 4; ++q) acc[mi][t][q] = 0.0f;

    const uint2* fp = frag + (size_t)tBase * 32 + lane;
    uint2 bf[8];
    if (PF) {
        #pragma unroll
        for (int t = 0; t < 8; ++t) bf[t] = __ldg(fp + t * 32);
    }
    #pragma unroll 1
    for (int kt = 0; kt < 16; ++kt) {
        if (!PF) {
            #pragma unroll
            for (int t = 0; t < 8; ++t) bf[t] = __ldg(fp + kt * 1024 + t * 32);
        }
        unsigned a0[4], a1[4];
        ldsm_x4(a0, lm0 + kt * 32);
        ldsm_x4(a1, lm1 + kt * 32);
        uint2 bfn[8];
        if (PF && kt < 15) {
            #pragma unroll
            for (int t = 0; t < 8; ++t) bfn[t] = __ldg(fp + (kt + 1) * 1024 + t * 32);
        }
        #pragma unroll
        for (int t = 0; t < 8; ++t) {
            mma16816(acc[0][t], a0[0], a0[1], a0[2], a0[3], bf[t].x, bf[t].y);
            mma16816(acc[1][t], a1[0], a1[1], a1[2], a1[3], bf[t].x, bf[t].y);
        }
        if (PF && kt < 15) {
            #pragma unroll
            for (int t = 0; t < 8; ++t) bf[t] = bfn[t];
        }
    }
}

// ---------------- K3: main fused kernel, one CTA per (b,m), 256 threads ----------------
__global__ void __launch_bounds__(256, 2) main_kernel(
    const float* __restrict__ key_edge,
    const float* __restrict__ bk, const float* __restrict__ be,
    const float* __restrict__ bn,
    float* __restrict__ out)
{
    extern __shared__ char sm[];
    __half* sA   = (__half*)(sm + SA_OFF);
    float* sQW   = (float*)(sm + SQW_OFF);
    float* sAttn = (float*)(sm + SATTN_OFF);
    float* sNode = (float*)(sm + SNODE_OFF);
    float* sBk   = (float*)(sm + SBIAS_OFF);
    float* sBe   = sBk + 256;

    const int tid = threadIdx.x, lane = tid & 31, warp = tid >> 5;
    const int bm = blockIdx.x, b = bm >> 7;

    sBk[tid] = bk[tid];
    sBe[tid] = be[tid];
    for (int i = tid; i < Hv * Dv; i += 256)
        sQW[(i >> 8) * 260 + (i & 255)] = g_qW[(size_t)bm * (Hv * Dv) + i];

    // ---- phase 1: KE (fp32 global) -> sA (fp16) ----
    const float* keb = key_edge + (size_t)bm * (Nv * Dv);
    {
        const int r4 = tid >> 6, c4 = (tid & 63) * 4;
        #pragma unroll 4
        for (int rr = 0; rr < 128; rr += 4) {
            int row = rr + r4;
            float4 v = *(const float4*)&keb[(size_t)row * Dv + c4];
            uint2 p;
            p.x = h2pack(__floats2half2_rn(v.x, v.y));
            p.y = h2pack(__floats2half2_rn(v.z, v.w));
            *(uint2*)&sA[row * PITCH + c4] = p;
        }
    }
    __syncthreads();

    // ldmatrix lane-address helpers
    const int rowsel = (lane & 7) + ((lane >> 3) & 1) * 8;
    const int colsel = (lane >> 4) * 8;
    const uint32_t smbA = smem_u32(sA);

    // ---- phase 2: scores via MMA: s[128n x 8h] = KE(fp16) @ qW^T(hi+lo) ----
    {
        uint32_t lmS = smbA + (uint32_t)(((warp * 16 + rowsel) * PITCH + colsel) * 2);
        const int hB  = lane >> 2;           // head column for B fragment
        const int kq2 = (lane & 3) * 2;
        float sc[4] = {0.0f, 0.0f, 0.0f, 0.0f};
        #pragma unroll 1
        for (int kt = 0; kt < 16; ++kt) {
            unsigned a[4];
            ldsm_x4(a, lmS + kt * 32);
            float2 qa = *(float2*)&sQW[hB * 260 + kt * 16 + kq2];
            float2 qb = *(float2*)&sQW[hB * 260 + kt * 16 + kq2 + 8];
            __half2 ha = __floats2half2_rn(qa.x, qa.y);
            __half2 hb = __floats2half2_rn(qb.x, qb.y);
            float2 ra = __half22float2(ha), rb = __half22float2(hb);
            __half2 la = __floats2half2_rn(qa.x - ra.x, qa.y - ra.y);
            __half2 lb = __floats2half2_rn(qb.x - rb.x, qb.y - rb.y);
            mma16816(sc, a[0], a[1], a[2], a[3], h2pack(ha), h2pack(hb));
            mma16816(sc, a[0], a[1], a[2], a[3], h2pack(la), h2pack(lb));
        }
        int rD = warp * 16 + (lane >> 2);
        int hD = (lane & 3) * 2;
        sAttn[hD * 128 + rD]           = sc[0];
        sAttn[(hD + 1) * 128 + rD]     = sc[1];
        sAttn[hD * 128 + rD + 8]       = sc[2];
        sAttn[(hD + 1) * 128 + rD + 8] = sc[3];
    }
    __syncthreads();

    // ---- softmax (warp per head) ----
    {
        int h = warp;
        float s[4];
        #pragma unroll
        for (int i = 0; i < 4; ++i) s[i] = sAttn[h * 128 + lane + 32 * i];
        float mx = fmaxf(fmaxf(s[0], s[1]), fmaxf(s[2], s[3]));
        #pragma unroll
        for (int off = 16; off > 0; off >>= 1)
            mx = fmaxf(mx, __shfl_xor_sync(0xffffffffu, mx, off));
        float e[4], sum = 0.0f;
        #pragma unroll
        for (int i = 0; i < 4; ++i) { e[i] = __expf(s[i] - mx); sum += e[i]; }
        #pragma unroll
        for (int off = 16; off > 0; off >>= 1)
            sum += __shfl_xor_sync(0xffffffffu, sum, off);
        float inv = __fdividef(1.0f, sum);
        #pragma unroll
        for (int i = 0; i < 4; ++i) sAttn[h * 128 + lane + 32 * i] = e[i] * inv;
    }
    __syncthreads();

    // ---- node path ----
    {
        int h = tid >> 5;
        const float* vp = g_vproj + (size_t)b * Nv * Dv + tid;
        float acc = 0.0f;
        for (int n = 0; n < Nv; ++n)
            acc += sAttn[h * 128 + n] * vp[(size_t)n * Dv];
        sNode[tid] = acc;
        __syncthreads();
        float acc2 = bn[tid];
        for (int d = 0; d < Dv; ++d)
            acc2 += sNode[d] * g_WnT[d * Dv + tid];
        out[EDGE_ELEMS + (size_t)bm * Dv + tid] = mishf(acc2);
    }
    __syncthreads();

    // ---- GEMM setup ----
    const int wi = warp & 3;                 // m-band: rows [wi*32, wi*32+32)
    const int wj = warp >> 2;                // n-group: cols [wj*64, wj*64+64) per np
    const int rA = lane >> 2;                // 0..7
    const int kq = (lane & 3) * 2;           // 0,2,4,6
    const uint32_t lm0 = smbA + (uint32_t)(((wi * 32 + rowsel) * PITCH + colsel) * 2);
    const uint32_t lm1 = lm0 + 16 * PITCH * 2;

    float acc[2][8][4];
    unsigned pk0[2][8][2];

    // ---- GEMM1 np=0 (prefetched) ----
    gemm_pass<true>(acc, lm0, lm1, g_fragK2, 0 * 16 + wj * 8, lane);
    #pragma unroll
    for (int mi = 0; mi < 2; ++mi) {
        #pragma unroll
        for (int t = 0; t < 8; ++t) {
            int r0 = wi * 32 + mi * 16 + rA;
            int c  = wj * 64 + t * 8 + kq;
            float b0 = sBk[c], b1 = sBk[c + 1];
            const float* attc = &sAttn[(c >> 5) * 128];
            float a0 = attc[r0], a8 = attc[r0 + 8];
            pk0[mi][t][0] = h2pack(__floats2half2_rn((acc[mi][t][0] + b0) * a0, (acc[mi][t][1] + b1) * a0));
            pk0[mi][t][1] = h2pack(__floats2half2_rn((acc[mi][t][2] + b0) * a8, (acc[mi][t][3] + b1) * a8));
        }
    }

    // ---- GEMM1 np=1 (no prefetch: pk0 live) ----
    gemm_pass<false>(acc, lm0, lm1, g_fragK2, 1 * 16 + wj * 8, lane);
    __syncthreads();   // all ldmatrix reads of sA (KE) complete

    // write A2 = scaled k (fp16) over sA
    #pragma unroll
    for (int mi = 0; mi < 2; ++mi) {
        #pragma unroll
        for (int t = 0; t < 8; ++t) {
            int r0 = wi * 32 + mi * 16 + rA;
            int c0 = wj * 64 + t * 8 + kq;
            int c1 = 128 + c0;
            *(unsigned*)&sA[r0 * PITCH + c0]       = pk0[mi][t][0];
            *(unsigned*)&sA[(r0 + 8) * PITCH + c0] = pk0[mi][t][1];
            float b0 = sBk[c1], b1 = sBk[c1 + 1];
            const float* attc = &sAttn[(c1 >> 5) * 128];
            float a0 = attc[r0], a8 = attc[r0 + 8];
            *(unsigned*)&sA[r0 * PITCH + c1] =
                h2pack(__floats2half2_rn((acc[mi][t][0] + b0) * a0, (acc[mi][t][1] + b1) * a0));
            *(unsigned*)&sA[(r0 + 8) * PITCH + c1] =
                h2pack(__floats2half2_rn((acc[mi][t][2] + b0) * a8, (acc[mi][t][3] + b1) * a8));
        }
    }
    __syncthreads();   // A2 visible to all warps

    // ---- GEMM2: out = mish(A2 @ We^T + be) ----
    #pragma unroll 1
    for (int np = 0; np < 2; ++np) {
        gemm_pass<true>(acc, lm0, lm1, g_fragE2, np * 16 + wj * 8, lane);
        #pragma unroll
        for (int mi = 0; mi < 2; ++mi) {
            #pragma unroll
            for (int t = 0; t < 8; ++t) {
                int r0 = wi * 32 + mi * 16 + rA;
                int c  = np * 128 + wj * 64 + t * 8 + kq;
                float b0 = sBe[c], b1 = sBe[c + 1];
                float2 o0, o1;
                o0.x = mishf(acc[mi][t][0] + b0);
                o0.y = mishf(acc[mi][t][1] + b1);
                o1.x = mishf(acc[mi][t][2] + b0);
                o1.y = mishf(acc[mi][t][3] + b1);
                *(float2*)&out[((size_t)bm * Nv + r0) * Dv + c]     = o0;
                *(float2*)&out[((size_t)bm * Nv + r0 + 8) * Dv + c] = o1;
            }
        }
    }
}

// ---------------------------------------------------------------------------
extern "C" void kernel_launch(void* const* d_in, const int* in_sizes, int n_in,
                              void* d_out, int out_size) {
    (void)in_sizes; (void)n_in; (void)out_size;
    const float* qn = (const float*)d_in[0];
    const float* vn = (const float*)d_in[1];
    const float* ke = (const float*)d_in[2];
    const float* Wq = (const float*)d_in[4];
    const float* bq = (const float*)d_in[5];
    const float* Wk = (const float*)d_in[6];
    const float* bk = (const float*)d_in[7];
    const float* Wv = (const float*)d_in[8];
    const float* bv = (const float*)d_in[9];
    const float* We = (const float*)d_in[10];
    const float* be = (const float*)d_in[11];
    const float* Wn = (const float*)d_in[12];
    const float* bn = (const float*)d_in[13];
    float* out = (float*)d_out;

    wprep_kernel<<<320, 256>>>(Wq, Wv, Wn, Wk, We);
    prep_kernel<<<BM, 256>>>(qn, vn, Wk, bq, bv);

    cudaFuncSetAttribute(main_kernel, cudaFuncAttributeMaxDynamicSharedMemorySize, SMEM_TOTAL);
    main_kernel<<<BM, 256, SMEM_TOTAL>>>(ke, bk, be, bn, out);
}